// round 2
// baseline (speedup 1.0000x reference)
#include <cuda_runtime.h>

typedef unsigned long long u64;

#define BATCH 32
#define NSEQ  2048
#define F     32
#define SPLITS 16
#define ROWS1 128               // rows per kernel-1 block
#define ROWS2 128               // rows per kernel-2 block
#define INV_N (1.0f / 2048.0f)

// Scratch: per-(batch,split) partial M = phi^T @ u (32x32 each).
// Fully overwritten by kernel 1 every launch -> deterministic.
__device__ float g_Mpart[BATCH * SPLITS * F * F];

// ---- packed f32x2 helpers (PTX-only; ptxas never auto-fuses FFMA2) ----
__device__ __forceinline__ u64 pk2(float a, float b) {
    u64 r; asm("mov.b64 %0,{%1,%2};" : "=l"(r) : "f"(a), "f"(b)); return r;
}
__device__ __forceinline__ float2 up2(u64 v) {
    float2 f; asm("mov.b64 {%0,%1},%2;" : "=f"(f.x), "=f"(f.y) : "l"(v)); return f;
}
__device__ __forceinline__ u64 ffma2(u64 a, u64 b, u64 c) {
    u64 d; asm("fma.rn.f32x2 %0,%1,%2,%3;" : "=l"(d) : "l"(a), "l"(b), "l"(c)); return d;
}
__device__ __forceinline__ u64 fmul2(u64 a, u64 b) {
    u64 d; asm("mul.rn.f32x2 %0,%1,%2;" : "=l"(d) : "l"(a), "l"(b)); return d;
}

// ---------------------------------------------------------------------------
// Kernel 1: partial M_b = sum_j phi_j (outer) u_j over a 128-row slice.
// ---------------------------------------------------------------------------
__global__ __launch_bounds__(ROWS1, 4) void k_partialM(
    const float* __restrict__ x,
    const float* __restrict__ w_phi, const float* __restrict__ b_phi,
    const float* __restrict__ w_u,   const float* __restrict__ b_u)
{
    __shared__ alignas(16) float ws_phi[F * F], ws_u[F * F];
    __shared__ alignas(16) float bs_phi[F], bs_u[F];
    // [j][f] layout, stride 34 (even -> 8B-aligned rows, conflict-free)
    __shared__ alignas(16) float phi_s[ROWS1 * 34];
    __shared__ alignas(16) float u_s[ROWS1 * 34];

    const int b     = blockIdx.x;
    const int split = blockIdx.y;
    const int t     = threadIdx.x;

    for (int i = t; i < F * F; i += ROWS1) {
        ws_phi[i] = w_phi[i];
        ws_u[i]   = w_u[i];
    }
    if (t < F) { bs_phi[t] = b_phi[t]; bs_u[t] = b_u[t]; }
    __syncthreads();

    // ---- Phase A: per-thread row -> phi, u (packed f32x2) ----
    const int row = split * ROWS1 + t;
    const float4* xr = (const float4*)(x + ((size_t)b * NSEQ + row) * F);
    float xv[F];
#pragma unroll
    for (int i = 0; i < 8; i++) {
        float4 v = xr[i];
        xv[4*i+0] = v.x; xv[4*i+1] = v.y; xv[4*i+2] = v.z; xv[4*i+3] = v.w;
    }

    u64 ph[16], uv[16];
#pragma unroll
    for (int i = 0; i < 16; i++) {
        ph[i] = ((const u64*)bs_phi)[i];
        uv[i] = ((const u64*)bs_u)[i];
    }
#pragma unroll
    for (int k = 0; k < F; k++) {
        const u64 xk2 = pk2(xv[k], xv[k]);
        const ulonglong2* wp = (const ulonglong2*)(ws_phi + k * F);
        const ulonglong2* wu = (const ulonglong2*)(ws_u   + k * F);
#pragma unroll
        for (int q = 0; q < 8; q++) {
            ulonglong2 a = wp[q];
            ph[2*q+0] = ffma2(xk2, a.x, ph[2*q+0]);
            ph[2*q+1] = ffma2(xk2, a.y, ph[2*q+1]);
            ulonglong2 c = wu[q];
            uv[2*q+0] = ffma2(xk2, c.x, uv[2*q+0]);
            uv[2*q+1] = ffma2(xk2, c.y, uv[2*q+1]);
        }
    }
    // relu + stage to smem ([j][f] layout)
    u64* prow = (u64*)(phi_s + t * 34);
    u64* urow = (u64*)(u_s   + t * 34);
#pragma unroll
    for (int i = 0; i < 16; i++) {
        prow[i] = ph[i];
        float2 tu = up2(uv[i]);
        urow[i] = pk2(fmaxf(tu.x, 0.0f), fmaxf(tu.y, 0.0f));
    }
    __syncthreads();

    // ---- Phase B: M[f1][f2] = sum_j phi[j][f1] * u[j][f2] ----
    // warp w owns f1 in [8w, 8w+8); lane owns f2. Pack over f1 pairs.
    const int lane = t & 31;
    const int w    = t >> 5;
    u64 acc2[4] = {0ull, 0ull, 0ull, 0ull};

#pragma unroll 4
    for (int j = 0; j < ROWS1; j++) {
        const float uj = u_s[j * 34 + lane];        // conflict-free
        const u64 uj2 = pk2(uj, uj);
        const u64* pr = (const u64*)(phi_s + j * 34 + w * 8);  // broadcast
#pragma unroll
        for (int q = 0; q < 4; q++)
            acc2[q] = ffma2(uj2, pr[q], acc2[q]);
    }

    float* mp = g_Mpart + ((size_t)(b * SPLITS + split)) * F * F;
#pragma unroll
    for (int q = 0; q < 4; q++) {
        float2 v = up2(acc2[q]);
        mp[(w * 8 + 2*q + 0) * F + lane] = v.x;
        mp[(w * 8 + 2*q + 1) * F + lane] = v.y;
    }
}

// ---------------------------------------------------------------------------
// Kernel 2: out_i = ((psi_i @ M - (psi_i . phi_i) * u_i) / N) @ w_r + x_i
// One thread per row, fully packed f32x2 math.
// ---------------------------------------------------------------------------
__global__ __launch_bounds__(ROWS2, 4) void k_main(
    const float* __restrict__ x,
    const float* __restrict__ w_psi, const float* __restrict__ b_psi,
    const float* __restrict__ w_phi, const float* __restrict__ b_phi,
    const float* __restrict__ w_u,   const float* __restrict__ b_u,
    const float* __restrict__ w_r,
    float* __restrict__ out)
{
    __shared__ alignas(16) float ws_psi[F * F], ws_phi[F * F], ws_u[F * F], ws_r[F * F];
    __shared__ alignas(16) float Ms[F * F];
    __shared__ alignas(16) float bs_psi[F], bs_phi[F], bs_u[F];

    const int blk   = blockIdx.x;
    const int b     = blk / (NSEQ / ROWS2);
    const int chunk = blk % (NSEQ / ROWS2);
    const int t     = threadIdx.x;

    for (int i = t; i < F * F; i += ROWS2) {
        ws_psi[i] = w_psi[i];
        ws_phi[i] = w_phi[i];
        ws_u[i]   = w_u[i];
        ws_r[i]   = w_r[i];
        float m = 0.0f;
        const float* mp = g_Mpart + (size_t)b * SPLITS * F * F + i;
#pragma unroll
        for (int s = 0; s < SPLITS; s++) m += mp[s * F * F];
        Ms[i] = m;
    }
    if (t < F) { bs_psi[t] = b_psi[t]; bs_phi[t] = b_phi[t]; bs_u[t] = b_u[t]; }
    __syncthreads();

    const int row = chunk * ROWS2 + t;
    const size_t g = (size_t)b * NSEQ + row;
    const float4* xr = (const float4*)(x + g * F);
    float xv[F];
#pragma unroll
    for (int i = 0; i < 8; i++) {
        float4 v = xr[i];
        xv[4*i+0] = v.x; xv[4*i+1] = v.y; xv[4*i+2] = v.z; xv[4*i+3] = v.w;
    }

    // ---- psi, u (packed) ----
    u64 ps[16], uv[16];
#pragma unroll
    for (int i = 0; i < 16; i++) {
        ps[i] = ((const u64*)bs_psi)[i];
        uv[i] = ((const u64*)bs_u)[i];
    }
#pragma unroll
    for (int k = 0; k < F; k++) {
        const u64 xk2 = pk2(xv[k], xv[k]);
        const ulonglong2* wp = (const ulonglong2*)(ws_psi + k * F);
        const ulonglong2* wu = (const ulonglong2*)(ws_u   + k * F);
#pragma unroll
        for (int q = 0; q < 8; q++) {
            ulonglong2 a = wp[q];
            ps[2*q+0] = ffma2(xk2, a.x, ps[2*q+0]);
            ps[2*q+1] = ffma2(xk2, a.y, ps[2*q+1]);
            ulonglong2 c = wu[q];
            uv[2*q+0] = ffma2(xk2, c.x, uv[2*q+0]);
            uv[2*q+1] = ffma2(xk2, c.y, uv[2*q+1]);
        }
    }
    // relu (keep packed)
#pragma unroll
    for (int i = 0; i < 16; i++) {
        float2 tu = up2(uv[i]);
        uv[i] = pk2(fmaxf(tu.x, 0.0f), fmaxf(tu.y, 0.0f));
    }

    // ---- diag = psi . phi = psi.b_phi + sum_k x_k * dot(psi, W_phi[k,:]) ----
    u64 dac = 0ull;
#pragma unroll
    for (int i = 0; i < 16; i++)
        dac = ffma2(ps[i], ((const u64*)bs_phi)[i], dac);
    float2 dd = up2(dac);
    float diag = dd.x + dd.y;
#pragma unroll
    for (int k = 0; k < F; k++) {
        u64 t0 = 0ull, t1 = 0ull;
        const ulonglong2* wf = (const ulonglong2*)(ws_phi + k * F);
#pragma unroll
        for (int q = 0; q < 8; q++) {
            ulonglong2 a = wf[q];
            t0 = ffma2(ps[2*q+0], a.x, t0);
            t1 = ffma2(ps[2*q+1], a.y, t1);
        }
        float2 A = up2(t0), Bv = up2(t1);
        diag += xv[k] * ((A.x + A.y) + (Bv.x + Bv.y));
    }

    // ---- o starts as residual x (packed); xv dies here ----
    u64 o[16];
#pragma unroll
    for (int i = 0; i < 16; i++) o[i] = pk2(xv[2*i+0], xv[2*i+1]);

    // ---- att = -diag*u + psi @ M (packed); uv dies after init ----
    u64 at[16];
    const u64 nd2 = pk2(-diag, -diag);
#pragma unroll
    for (int i = 0; i < 16; i++) at[i] = fmul2(nd2, uv[i]);

    float psv[F];
#pragma unroll
    for (int i = 0; i < 16; i++) {
        float2 tp = up2(ps[i]);
        psv[2*i+0] = tp.x; psv[2*i+1] = tp.y;
    }
#pragma unroll
    for (int k = 0; k < F; k++) {
        const u64 pkk = pk2(psv[k], psv[k]);
        const ulonglong2* mm = (const ulonglong2*)(Ms + k * F);
#pragma unroll
        for (int q = 0; q < 8; q++) {
            ulonglong2 a = mm[q];
            at[2*q+0] = ffma2(pkk, a.x, at[2*q+0]);
            at[2*q+1] = ffma2(pkk, a.y, at[2*q+1]);
        }
    }

    // ---- scale by 1/N, unpack att to scalars ----
    float av[F];
    const u64 iv2 = pk2(INV_N, INV_N);
#pragma unroll
    for (int i = 0; i < 16; i++) {
        float2 ta = up2(fmul2(at[i], iv2));
        av[2*i+0] = ta.x; av[2*i+1] = ta.y;
    }

    // ---- o += att @ w_r ----
#pragma unroll
    for (int k = 0; k < F; k++) {
        const u64 ak2 = pk2(av[k], av[k]);
        const ulonglong2* wr = (const ulonglong2*)(ws_r + k * F);
#pragma unroll
        for (int q = 0; q < 8; q++) {
            ulonglong2 a = wr[q];
            o[2*q+0] = ffma2(ak2, a.x, o[2*q+0]);
            o[2*q+1] = ffma2(ak2, a.y, o[2*q+1]);
        }
    }

    ulonglong2* orow = (ulonglong2*)(out + g * F);
#pragma unroll
    for (int q = 0; q < 8; q++) {
        ulonglong2 v; v.x = o[2*q+0]; v.y = o[2*q+1];
        orow[q] = v;
    }
}

// ---------------------------------------------------------------------------
extern "C" void kernel_launch(void* const* d_in, const int* in_sizes, int n_in,
                              void* d_out, int out_size)
{
    const float* x     = (const float*)d_in[0];
    const float* w_psi = (const float*)d_in[1];
    const float* b_psi = (const float*)d_in[2];
    const float* w_phi = (const float*)d_in[3];
    const float* b_phi = (const float*)d_in[4];
    const float* w_u   = (const float*)d_in[5];
    const float* b_u   = (const float*)d_in[6];
    const float* w_r   = (const float*)d_in[7];
    float* out = (float*)d_out;

    dim3 g1(BATCH, SPLITS);
    k_partialM<<<g1, ROWS1>>>(x, w_phi, b_phi, w_u, b_u);
    k_main<<<BATCH * (NSEQ / ROWS2), ROWS2>>>(x, w_psi, b_psi, w_phi, b_phi,
                                              w_u, b_u, w_r, out);
}

// round 5
// speedup vs baseline: 1.5403x; 1.5403x over previous
#include <cuda_runtime.h>

typedef unsigned long long u64;

#define BATCH 32
#define NSEQ  2048
#define F     32
#define SPLITS 16
#define ROWS1 (NSEQ / SPLITS)   // 128 rows per kernel-1 block
#define INV_N (1.0f / 2048.0f)

// Scratch (overwritten fully every launch -> deterministic)
__device__ float g_Mpart[BATCH * SPLITS * F * F];
__device__ float g_M[BATCH * F * F];

// ---- packed f32x2 helpers ----
__device__ __forceinline__ u64 pk2(float a, float b) {
    u64 r; asm("mov.b64 %0,{%1,%2};" : "=l"(r) : "f"(a), "f"(b)); return r;
}
__device__ __forceinline__ float2 up2(u64 v) {
    float2 f; asm("mov.b64 {%0,%1},%2;" : "=f"(f.x), "=f"(f.y) : "l"(v)); return f;
}
__device__ __forceinline__ u64 ffma2(u64 a, u64 b, u64 c) {
    u64 d; asm("fma.rn.f32x2 %0,%1,%2,%3;" : "=l"(d) : "l"(a), "l"(b), "l"(c)); return d;
}
__device__ __forceinline__ u64 fmul2(u64 a, u64 b) {
    u64 d; asm("mul.rn.f32x2 %0,%1,%2;" : "=l"(d) : "l"(a), "l"(b)); return d;
}

// ---------------------------------------------------------------------------
// Kernel 1 (R1-proven): partial M_b = sum_j phi_j (outer) u_j, 128-row slice.
// ---------------------------------------------------------------------------
__global__ __launch_bounds__(ROWS1) void k_partialM(
    const float* __restrict__ x,
    const float* __restrict__ w_phi, const float* __restrict__ b_phi,
    const float* __restrict__ w_u,   const float* __restrict__ b_u)
{
    __shared__ float ws_phi[F * F], ws_u[F * F];
    __shared__ float bs_phi[F], bs_u[F];
    __shared__ float phi_s[F * 129];
    __shared__ float u_s[F * 129];

    const int b     = blockIdx.x;
    const int split = blockIdx.y;
    const int t     = threadIdx.x;

    for (int i = t; i < F * F; i += ROWS1) {
        ws_phi[i] = w_phi[i];
        ws_u[i]   = w_u[i];
    }
    if (t < F) { bs_phi[t] = b_phi[t]; bs_u[t] = b_u[t]; }
    __syncthreads();

    const int row = split * ROWS1 + t;
    const float4* xr = (const float4*)(x + ((size_t)b * NSEQ + row) * F);
    float xv[F];
#pragma unroll
    for (int i = 0; i < 8; i++) {
        float4 v = xr[i];
        xv[4*i+0] = v.x; xv[4*i+1] = v.y; xv[4*i+2] = v.z; xv[4*i+3] = v.w;
    }

    float phi[F], uu[F];
#pragma unroll
    for (int f = 0; f < F; f++) { phi[f] = bs_phi[f]; uu[f] = bs_u[f]; }

#pragma unroll
    for (int k = 0; k < F; k++) {
        const float xk = xv[k];
#pragma unroll
        for (int f4 = 0; f4 < 8; f4++) {
            float4 wp = *(const float4*)(ws_phi + k * F + 4 * f4);
            float4 wv = *(const float4*)(ws_u   + k * F + 4 * f4);
            phi[4*f4+0] += xk * wp.x; phi[4*f4+1] += xk * wp.y;
            phi[4*f4+2] += xk * wp.z; phi[4*f4+3] += xk * wp.w;
            uu [4*f4+0] += xk * wv.x; uu [4*f4+1] += xk * wv.y;
            uu [4*f4+2] += xk * wv.z; uu [4*f4+3] += xk * wv.w;
        }
    }
#pragma unroll
    for (int f = 0; f < F; f++) {
        uu[f] = fmaxf(uu[f], 0.0f);
        phi_s[f * 129 + t] = phi[f];
        u_s  [f * 129 + t] = uu[f];
    }
    __syncthreads();

    const int lane = t & 31;
    const int w    = t >> 5;
    float acc[8];
#pragma unroll
    for (int r = 0; r < 8; r++) acc[r] = 0.0f;

#pragma unroll 4
    for (int j = 0; j < ROWS1; j++) {
        const float uvv = u_s[lane * 129 + j];
#pragma unroll
        for (int r = 0; r < 8; r++)
            acc[r] += phi_s[(w * 8 + r) * 129 + j] * uvv;
    }

    float* mp = g_Mpart + ((size_t)(b * SPLITS + split)) * F * F;
#pragma unroll
    for (int r = 0; r < 8; r++)
        mp[(w * 8 + r) * F + lane] = acc[r];
}

// ---------------------------------------------------------------------------
// Kernel 1b: reduce 16 partials -> g_M[b][32][32]
// ---------------------------------------------------------------------------
__global__ __launch_bounds__(256) void k_reduceM()
{
    const int b = blockIdx.x;
    for (int e = threadIdx.x; e < F * F; e += 256) {
        float s = 0.0f;
        const float* mp = g_Mpart + (size_t)b * SPLITS * F * F + e;
#pragma unroll
        for (int sp = 0; sp < SPLITS; sp++) s += mp[sp * F * F];
        g_M[b * F * F + e] = s;
    }
}

// ---------------------------------------------------------------------------
// Kernel 2: out_i = ((psi_i @ M - (psi_i . phi_i) * u_i)/N) @ w_r + x_i
// 2 threads per row (16 features each). Block = 128 thr = 64 rows.
// Grid = 1024 blocks -> ~7 blocks/SM resident.
// ---------------------------------------------------------------------------
// shared pool offsets (floats)
#define O_WPSI 0
#define O_WPHI 1024
#define O_WU   2048
#define O_WR   3072
#define O_MS   4096
#define O_BPSI 5120
#define O_BPHI 5152
#define O_BU   5184
#define O_XS   5216            // 64*33 = 2112 floats; also aliased as att_s
#define POOL_F 7328
// aliases (valid after sync #0: weights psi/phi/u no longer read)
#define O_PSIS 0               // 2112 floats over ws_psi/ws_phi/part of ws_u
#define O_DIAG 2176            // 128 floats, still inside dead ws_u

__global__ __launch_bounds__(128) void k_main(
    const float* __restrict__ x,
    const float* __restrict__ w_psi, const float* __restrict__ b_psi,
    const float* __restrict__ w_phi, const float* __restrict__ b_phi,
    const float* __restrict__ w_u,   const float* __restrict__ b_u,
    const float* __restrict__ w_r,
    float* __restrict__ out)
{
    __shared__ alignas(16) float pool[POOL_F];

    const int b     = blockIdx.x >> 5;          // 32 chunks per batch
    const int chunk = blockIdx.x & 31;
    const int t     = threadIdx.x;
    const int half  = t >> 6;                   // warps 0,1 -> half 0; 2,3 -> half 1
    const int r     = t & 63;                   // local row

    // ---- cooperative loads ----
#pragma unroll
    for (int i = t; i < 256; i += 128) {
        ((float4*)(pool + O_WPSI))[i] = ((const float4*)w_psi)[i];
        ((float4*)(pool + O_WPHI))[i] = ((const float4*)w_phi)[i];
        ((float4*)(pool + O_WU  ))[i] = ((const float4*)w_u  )[i];
        ((float4*)(pool + O_WR  ))[i] = ((const float4*)w_r  )[i];
        ((float4*)(pool + O_MS  ))[i] = ((const float4*)(g_M + (size_t)b * F * F))[i];
    }
    if (t < F) {
        pool[O_BPSI + t] = b_psi[t];
        pool[O_BPHI + t] = b_phi[t];
        pool[O_BU   + t] = b_u[t];
    }
    // stage x tile: 64 rows x 32 floats, smem stride 33
    {
        const float* xg = x + ((size_t)b * NSEQ + chunk * 64) * F;
#pragma unroll
        for (int i = t; i < 512; i += 128) {
            int row = i >> 3, c = (i & 7) << 2;
            float4 v = ((const float4*)xg)[i];
            pool[O_XS + row * 33 + c + 0] = v.x;
            pool[O_XS + row * 33 + c + 1] = v.y;
            pool[O_XS + row * 33 + c + 2] = v.z;
            pool[O_XS + row * 33 + c + 3] = v.w;
        }
    }
    __syncthreads();

    // ---- loop1: psi/phi/u half-rows (packed f32x2) ----
    u64 ps[8], ph[8], uv[8];
#pragma unroll
    for (int i = 0; i < 8; i++) {
        ps[i] = ((const u64*)(pool + O_BPSI))[half * 8 + i];
        ph[i] = ((const u64*)(pool + O_BPHI))[half * 8 + i];
        uv[i] = ((const u64*)(pool + O_BU  ))[half * 8 + i];
    }
    const int hoff = half * 16;
#pragma unroll
    for (int k = 0; k < F; k++) {
        const float xk = pool[O_XS + r * 33 + k];
        const u64 xk2 = pk2(xk, xk);
        const ulonglong2* wp = (const ulonglong2*)(pool + O_WPSI + k * F + hoff);
        const ulonglong2* wf = (const ulonglong2*)(pool + O_WPHI + k * F + hoff);
        const ulonglong2* wu = (const ulonglong2*)(pool + O_WU   + k * F + hoff);
#pragma unroll
        for (int q = 0; q < 4; q++) {
            ulonglong2 a = wp[q];
            ps[2*q+0] = ffma2(xk2, a.x, ps[2*q+0]);
            ps[2*q+1] = ffma2(xk2, a.y, ps[2*q+1]);
        }
#pragma unroll
        for (int q = 0; q < 4; q++) {
            ulonglong2 a = wf[q];
            ph[2*q+0] = ffma2(xk2, a.x, ph[2*q+0]);
            ph[2*q+1] = ffma2(xk2, a.y, ph[2*q+1]);
        }
#pragma unroll
        for (int q = 0; q < 4; q++) {
            ulonglong2 a = wu[q];
            uv[2*q+0] = ffma2(xk2, a.x, uv[2*q+0]);
            uv[2*q+1] = ffma2(xk2, a.y, uv[2*q+1]);
        }
    }
    // relu
#pragma unroll
    for (int i = 0; i < 8; i++) {
        float2 tu = up2(uv[i]);
        uv[i] = pk2(fmaxf(tu.x, 0.0f), fmaxf(tu.y, 0.0f));
    }
    // partial diag = dot(psi_half, phi_half)
    u64 dac = 0ull;
#pragma unroll
    for (int i = 0; i < 8; i++) dac = ffma2(ps[i], ph[i], dac);
    float2 dd = up2(dac);
    const float dpart = dd.x + dd.y;

    __syncthreads();   // #0: weights psi/phi/u and x_s loop1 reads complete

    // stage psi + diag partial (aliased region)
#pragma unroll
    for (int i = 0; i < 8; i++) {
        float2 p = up2(ps[i]);
        pool[O_PSIS + r * 33 + hoff + 2*i + 0] = p.x;
        pool[O_PSIS + r * 33 + hoff + 2*i + 1] = p.y;
    }
    pool[O_DIAG + r * 2 + half] = dpart;
    __syncthreads();   // #1

    const float diag = pool[O_DIAG + r * 2] + pool[O_DIAG + r * 2 + 1];

    // ---- att_half = (psi @ M - diag*u) * invN ----
    u64 at[8];
    const u64 nd2 = pk2(-diag, -diag);
#pragma unroll
    for (int i = 0; i < 8; i++) at[i] = fmul2(nd2, uv[i]);
#pragma unroll
    for (int k = 0; k < F; k++) {
        const float pkv = pool[O_PSIS + r * 33 + k];
        const u64 pk2v = pk2(pkv, pkv);
        const ulonglong2* mm = (const ulonglong2*)(pool + O_MS + k * F + hoff);
#pragma unroll
        for (int q = 0; q < 4; q++) {
            ulonglong2 a = mm[q];
            at[2*q+0] = ffma2(pk2v, a.x, at[2*q+0]);
            at[2*q+1] = ffma2(pk2v, a.y, at[2*q+1]);
        }
    }
    const u64 iv2 = pk2(INV_N, INV_N);
#pragma unroll
    for (int i = 0; i < 8; i++) at[i] = fmul2(at[i], iv2);

    // stage att over x_s (all x_s reads completed before sync #0)
#pragma unroll
    for (int i = 0; i < 8; i++) {
        float2 a = up2(at[i]);
        pool[O_XS + r * 33 + hoff + 2*i + 0] = a.x;
        pool[O_XS + r * 33 + hoff + 2*i + 1] = a.y;
    }
    __syncthreads();   // #2

    // ---- o = x (global reload, L2-hot) + att @ w_r ----
    const size_t g = ((size_t)b * NSEQ + chunk * 64 + r) * F + hoff;
    u64 o[8];
#pragma unroll
    for (int q = 0; q < 4; q++) {
        float4 v = ((const float4*)(x + g))[q];
        o[2*q+0] = pk2(v.x, v.y);
        o[2*q+1] = pk2(v.z, v.w);
    }
#pragma unroll
    for (int k = 0; k < F; k++) {
        const float ak = pool[O_XS + r * 33 + k];
        const u64 ak2 = pk2(ak, ak);
        const ulonglong2* wr = (const ulonglong2*)(pool + O_WR + k * F + hoff);
#pragma unroll
        for (int q = 0; q < 4; q++) {
            ulonglong2 a = wr[q];
            o[2*q+0] = ffma2(ak2, a.x, o[2*q+0]);
            o[2*q+1] = ffma2(ak2, a.y, o[2*q+1]);
        }
    }
#pragma unroll
    for (int q = 0; q < 4; q++) {
        float2 lo = up2(o[2*q+0]), hi = up2(o[2*q+1]);
        ((float4*)(out + g))[q] = make_float4(lo.x, lo.y, hi.x, hi.y);
    }
}

// ---------------------------------------------------------------------------
extern "C" void kernel_launch(void* const* d_in, const int* in_sizes, int n_in,
                              void* d_out, int out_size)
{
    const float* x     = (const float*)d_in[0];
    const float* w_psi = (const float*)d_in[1];
    const float* b_psi = (const float*)d_in[2];
    const float* w_phi = (const float*)d_in[3];
    const float* b_phi = (const float*)d_in[4];
    const float* w_u   = (const float*)d_in[5];
    const float* b_u   = (const float*)d_in[6];
    const float* w_r   = (const float*)d_in[7];
    float* out = (float*)d_out;

    dim3 g1(BATCH, SPLITS);
    k_partialM<<<g1, ROWS1>>>(x, w_phi, b_phi, w_u, b_u);
    k_reduceM<<<BATCH, 256>>>();
    k_main<<<BATCH * 32, 128>>>(x, w_psi, b_psi, w_phi, b_phi,
                                w_u, b_u, w_r, out);
}